// round 1
// baseline (speedup 1.0000x reference)
#include <cuda_runtime.h>

// Problem constants
#define HEADS   12
#define NTOK    49
#define HD      32
#define CDIM    384
#define NWIN    1024
#define BATCH   8192
#define MROWS   (8192*49)        // 401408

// Scratch: __device__ globals (no allocation allowed in kernel_launch)
__device__ float g_q[(long long)MROWS * CDIM];
__device__ float g_k[(long long)MROWS * CDIM];
__device__ float g_v[(long long)MROWS * CDIM];
__device__ float g_att[(long long)MROWS * CDIM];

// ---------------------------------------------------------------------------
// SGEMM: C = A(MxK) * B(KxN) + bias, output split into up-to-3 row-major
// 384-col tensors (for QKV: cols [0,384)->C0, [384,768)->C1, [768,1152)->C2).
// Tiling: 128x128x8, 256 threads, 8x8 per thread.
// Requires M%128==0, N%128==0, K%8==0, K%4==0 (all true here).
// ---------------------------------------------------------------------------
__global__ __launch_bounds__(256) void sgemm128(
    const float* __restrict__ A, const float* __restrict__ B,
    const float* __restrict__ bias,
    float* __restrict__ C0, float* __restrict__ C1, float* __restrict__ C2,
    int K, int N)
{
    const int BM = 128, BN = 128, BK = 8;
    __shared__ float As[BK][BM];
    __shared__ float Bs[BK][BN];

    const int tid = threadIdx.x;
    const int n0  = blockIdx.x * BN;
    const long long m0 = (long long)blockIdx.y * BM;

    const int tx = tid & 15;   // 0..15 -> 8 cols each
    const int ty = tid >> 4;   // 0..15 -> 8 rows each

    float acc[8][8];
#pragma unroll
    for (int i = 0; i < 8; i++)
#pragma unroll
        for (int j = 0; j < 8; j++) acc[i][j] = 0.0f;

    // A-tile load mapping: 128 rows x 8 cols = 1024 floats, float4 per thread
    const int aRow = tid >> 1;          // 0..127
    const int aCol = (tid & 1) * 4;     // 0 or 4
    // B-tile load mapping: 8 rows x 128 cols, float4 per thread
    const int bRow = tid >> 5;          // 0..7
    const int bCol = (tid & 31) * 4;    // 0..124

    const float* Aptr = A + (m0 + aRow) * (long long)K + aCol;
    const float* Bptr = B + (long long)bRow * N + n0 + bCol;

    for (int k0 = 0; k0 < K; k0 += BK) {
        float4 a = *(const float4*)(Aptr + k0);
        As[aCol + 0][aRow] = a.x;
        As[aCol + 1][aRow] = a.y;
        As[aCol + 2][aRow] = a.z;
        As[aCol + 3][aRow] = a.w;
        float4 bv = *(const float4*)(Bptr + (long long)k0 * N);
        *(float4*)&Bs[bRow][bCol] = bv;
        __syncthreads();

#pragma unroll
        for (int k = 0; k < BK; k++) {
            float4 a0 = *(const float4*)&As[k][ty * 8];
            float4 a1 = *(const float4*)&As[k][ty * 8 + 4];
            float4 b0 = *(const float4*)&Bs[k][tx * 8];
            float4 b1 = *(const float4*)&Bs[k][tx * 8 + 4];
            float ra[8] = {a0.x, a0.y, a0.z, a0.w, a1.x, a1.y, a1.z, a1.w};
            float rb[8] = {b0.x, b0.y, b0.z, b0.w, b1.x, b1.y, b1.z, b1.w};
#pragma unroll
            for (int i = 0; i < 8; i++)
#pragma unroll
                for (int j = 0; j < 8; j++)
                    acc[i][j] = fmaf(ra[i], rb[j], acc[i][j]);
        }
        __syncthreads();
    }

    // Epilogue: add bias, scatter to the right 384-col tensor
#pragma unroll
    for (int i = 0; i < 8; i++) {
        const long long row = m0 + ty * 8 + i;
#pragma unroll
        for (int j = 0; j < 8; j += 4) {
            const int c  = n0 + tx * 8 + j;          // global col in [0,N)
            const int s  = c / CDIM;                 // which output tensor
            const int cc = c - s * CDIM;             // col within tensor
            float* Cp = (s == 0) ? C0 : ((s == 1) ? C1 : C2);
            float4 v;
            v.x = acc[i][j + 0] + bias[c + 0];
            v.y = acc[i][j + 1] + bias[c + 1];
            v.z = acc[i][j + 2] + bias[c + 2];
            v.w = acc[i][j + 3] + bias[c + 3];
            *(float4*)(Cp + row * CDIM + cc) = v;
        }
    }
}

// ---------------------------------------------------------------------------
// Attention: one block per (window b, head h). 256 threads.
//   S = (q*scale) @ k^T + rel_bias[h] + mask[b % NWIN]
//   P = softmax(S);  O = P @ v  -> g_att[b][n][h*32+d]
// ---------------------------------------------------------------------------
__global__ __launch_bounds__(256) void attn_kernel(
    const float* __restrict__ mask, const float* __restrict__ rel_bias,
    float* __restrict__ attout)
{
    const int bh = blockIdx.x;
    const int b  = bh / HEADS;
    const int h  = bh - b * HEADS;
    const int w  = b & (NWIN - 1);

    // padded strides to avoid 32-float-stride bank conflicts on k^T reads
    __shared__ float qs[NTOK * 33];
    __shared__ float ks[NTOK * 33];
    __shared__ float vs[NTOK * HD];
    __shared__ float sm[NTOK][56];

    const int tid = threadIdx.x;
    const float scale = 0.17677669529663689f;   // 1/sqrt(32)

    const long long base = ((long long)b * NTOK) * CDIM + h * HD;
    for (int idx = tid; idx < NTOK * HD; idx += 256) {
        const int n = idx >> 5, d = idx & 31;
        const long long g = base + (long long)n * CDIM + d;
        qs[n * 33 + d] = g_q[g] * scale;
        ks[n * 33 + d] = g_k[g];
        vs[n * HD + d] = g_v[g];
    }
    __syncthreads();

    const float* rb = rel_bias + h * (NTOK * NTOK);
    const float* mk = mask + (long long)w * (NTOK * NTOK);

    for (int idx = tid; idx < NTOK * NTOK; idx += 256) {
        const int i = idx / NTOK;
        const int j = idx - i * NTOK;
        float acc = 0.0f;
#pragma unroll
        for (int k = 0; k < HD; k++)
            acc = fmaf(qs[i * 33 + k], ks[j * 33 + k], acc);
        sm[i][j] = acc + rb[idx] + mk[idx];
    }
    __syncthreads();

    // softmax: warp per row
    const int warp = tid >> 5, lane = tid & 31;
    for (int i = warp; i < NTOK; i += 8) {
        float m = -1e30f;
        for (int j = lane; j < NTOK; j += 32) m = fmaxf(m, sm[i][j]);
#pragma unroll
        for (int o = 16; o; o >>= 1) m = fmaxf(m, __shfl_xor_sync(0xffffffffu, m, o));
        float sum = 0.0f;
        for (int j = lane; j < NTOK; j += 32) {
            const float e = __expf(sm[i][j] - m);
            sm[i][j] = e;
            sum += e;
        }
#pragma unroll
        for (int o = 16; o; o >>= 1) sum += __shfl_xor_sync(0xffffffffu, sum, o);
        const float inv = 1.0f / sum;
        for (int j = lane; j < NTOK; j += 32) sm[i][j] *= inv;
    }
    __syncthreads();

    // O = P @ V
    for (int idx = tid; idx < NTOK * HD; idx += 256) {
        const int i = idx >> 5, d = idx & 31;
        float acc = 0.0f;
#pragma unroll
        for (int j = 0; j < NTOK; j++)
            acc = fmaf(sm[i][j], vs[j * HD + d], acc);
        attout[((long long)b * NTOK + i) * CDIM + h * HD + d] = acc;
    }
}

// ---------------------------------------------------------------------------
extern "C" void kernel_launch(void* const* d_in, const int* in_sizes, int n_in,
                              void* d_out, int out_size)
{
    (void)in_sizes; (void)n_in; (void)out_size;
    const float* x        = (const float*)d_in[0];
    const float* mask     = (const float*)d_in[1];
    const float* qkv_w    = (const float*)d_in[2];
    const float* qkv_b    = (const float*)d_in[3];
    const float* rel_bias = (const float*)d_in[4];
    const float* proj_w   = (const float*)d_in[5];
    const float* proj_b   = (const float*)d_in[6];
    float* out = (float*)d_out;

    float *gq, *gk, *gv, *ga;
    cudaGetSymbolAddress((void**)&gq, g_q);
    cudaGetSymbolAddress((void**)&gk, g_k);
    cudaGetSymbolAddress((void**)&gv, g_v);
    cudaGetSymbolAddress((void**)&ga, g_att);

    // 1) QKV projection: (401408 x 384) @ (384 x 1152) + qkv_b -> g_q/g_k/g_v
    {
        dim3 grid(3 * CDIM / 128, MROWS / 128);
        sgemm128<<<grid, 256>>>(x, qkv_w, qkv_b, gq, gk, gv, CDIM, 3 * CDIM);
    }
    // 2) Attention per (window, head)
    {
        attn_kernel<<<BATCH * HEADS, 256>>>(mask, rel_bias, ga);
    }
    // 3) Output projection: (401408 x 384) @ (384 x 384) + proj_b -> d_out
    {
        dim3 grid(CDIM / 128, MROWS / 128);
        sgemm128<<<grid, 256>>>(ga, proj_w, proj_b, out, out, out, CDIM, CDIM);
    }
}

// round 2
// speedup vs baseline: 2.1063x; 2.1063x over previous
#include <cuda_runtime.h>
#include <cstdint>

// Problem constants
#define HEADS   12
#define NTOK    49
#define HD      32
#define CDIM    384
#define NWIN    1024
#define BATCH   8192
#define MROWS   (8192*49)        // 401408

// Scratch: __device__ globals (no allocation allowed in kernel_launch)
__device__ float g_q[(long long)MROWS * CDIM];
__device__ float g_k[(long long)MROWS * CDIM];
__device__ float g_v[(long long)MROWS * CDIM];
__device__ float g_att[(long long)MROWS * CDIM];

// ---------------------------------------------------------------------------
// TF32 tensor-core GEMM: C = A(MxK) @ B(KxN) + bias, with the output columns
// routed to up to 3 separate row-major 384-col tensors (QKV split).
// Tile: 128x128x16, 256 threads (8 warps as 2m x 4n), warp tile 64x32,
// mma.sync.m16n8k8.tf32, fp32 accumulate. Inputs rounded with cvt.rna.tf32
// at the smem-store stage.
// Requires M%128==0, N%128==0, K%16==0.
// ---------------------------------------------------------------------------
__device__ __forceinline__ uint32_t f2tf32(float f) {
    uint32_t u;
    asm("cvt.rna.tf32.f32 %0, %1;" : "=r"(u) : "f"(f));
    return u;
}

__global__ __launch_bounds__(256, 2) void gemm_tf32(
    const float* __restrict__ A, const float* __restrict__ B,
    const float* __restrict__ bias,
    float* __restrict__ C0, float* __restrict__ C1, float* __restrict__ C2,
    int K, int N)
{
    __shared__ float As[128][20];    // [m][k], row stride 20 floats (16B aligned)
    __shared__ float Bs[16][132];    // [k][n], row stride 132 floats

    const int tid  = threadIdx.x;
    const int lane = tid & 31;
    const int wid  = tid >> 5;
    const int wm   = (wid & 1) * 64;    // warp m offset in tile
    const int wn   = (wid >> 1) * 32;   // warp n offset in tile

    const long long m0 = (long long)blockIdx.y * 128;
    const int       n0 = blockIdx.x * 128;

    // global-load mappings
    const int aRow = tid >> 2;          // 0..63 (plus +64 for 2nd chunk)
    const int aC4  = (tid & 3) * 4;     // k offset within 16
    const int bK   = tid >> 5;          // 0..7 (plus +8)
    const int bN   = (tid & 31) * 4;

    const float* Ap = A + (m0 + aRow) * (long long)K + aC4;
    const float* Bp = B + (long long)bK * N + n0 + bN;

    float acc[4][4][4];
#pragma unroll
    for (int i = 0; i < 4; i++)
#pragma unroll
        for (int j = 0; j < 4; j++)
#pragma unroll
            for (int r = 0; r < 4; r++) acc[i][j][r] = 0.0f;

    const int iters = K >> 4;   // K/16
    float4 pa0, pa1, pb0, pb1;

    // prefetch tile 0
    {
        pa0 = *(const float4*)(Ap);
        pa1 = *(const float4*)(Ap + 64 * (long long)K);
        pb0 = *(const float4*)(Bp);
        pb1 = *(const float4*)(Bp + 8LL * N);
    }
    // store tile 0
    {
        *(float4*)&As[aRow][aC4] = make_float4(
            __uint_as_float(f2tf32(pa0.x)), __uint_as_float(f2tf32(pa0.y)),
            __uint_as_float(f2tf32(pa0.z)), __uint_as_float(f2tf32(pa0.w)));
        *(float4*)&As[aRow + 64][aC4] = make_float4(
            __uint_as_float(f2tf32(pa1.x)), __uint_as_float(f2tf32(pa1.y)),
            __uint_as_float(f2tf32(pa1.z)), __uint_as_float(f2tf32(pa1.w)));
        *(float4*)&Bs[bK][bN] = make_float4(
            __uint_as_float(f2tf32(pb0.x)), __uint_as_float(f2tf32(pb0.y)),
            __uint_as_float(f2tf32(pb0.z)), __uint_as_float(f2tf32(pb0.w)));
        *(float4*)&Bs[bK + 8][bN] = make_float4(
            __uint_as_float(f2tf32(pb1.x)), __uint_as_float(f2tf32(pb1.y)),
            __uint_as_float(f2tf32(pb1.z)), __uint_as_float(f2tf32(pb1.w)));
    }
    __syncthreads();

    // ldmatrix lane mapping (constant across iterations)
    const int lg     = lane >> 3;                 // matrix id 0..3
    const int lr     = lane & 7;                  // row within matrix
    const int ldRow  = ((lg & 1) << 3) + lr;      // 0..15 within m16 tile
    const int ldKoff = (lg >> 1) << 2;            // 0 or 4

    for (int it = 0; it < iters; ++it) {
        // prefetch next tile into registers
        if (it + 1 < iters) {
            const long long kk = (long long)(it + 1) << 4;
            pa0 = *(const float4*)(Ap + kk);
            pa1 = *(const float4*)(Ap + 64 * (long long)K + kk);
            pb0 = *(const float4*)(Bp + kk * N);
            pb1 = *(const float4*)(Bp + (kk + 8) * N);
        }

        // compute on current smem tile: 2 k-steps of 8
#pragma unroll
        for (int ks = 0; ks < 2; ks++) {
            const int k0 = ks * 8;
            uint32_t af[4][4];
#pragma unroll
            for (int i = 0; i < 4; i++) {
                uint32_t saddr = (uint32_t)__cvta_generic_to_shared(
                    &As[wm + i * 16 + ldRow][k0 + ldKoff]);
                asm volatile(
                    "ldmatrix.sync.aligned.m8n8.x4.shared.b16 {%0,%1,%2,%3}, [%4];"
                    : "=r"(af[i][0]), "=r"(af[i][1]), "=r"(af[i][2]), "=r"(af[i][3])
                    : "r"(saddr));
            }
            uint32_t bf[4][2];
#pragma unroll
            for (int j = 0; j < 4; j++) {
                const int nn = wn + j * 8 + (lane >> 2);
                bf[j][0] = __float_as_uint(Bs[k0 + (lane & 3)][nn]);
                bf[j][1] = __float_as_uint(Bs[k0 + 4 + (lane & 3)][nn]);
            }
#pragma unroll
            for (int i = 0; i < 4; i++)
#pragma unroll
                for (int j = 0; j < 4; j++) {
                    asm volatile(
                        "mma.sync.aligned.m16n8k8.row.col.f32.tf32.tf32.f32 "
                        "{%0,%1,%2,%3}, {%4,%5,%6,%7}, {%8,%9}, {%0,%1,%2,%3};"
                        : "+f"(acc[i][j][0]), "+f"(acc[i][j][1]),
                          "+f"(acc[i][j][2]), "+f"(acc[i][j][3])
                        : "r"(af[i][0]), "r"(af[i][1]), "r"(af[i][2]), "r"(af[i][3]),
                          "r"(bf[j][0]), "r"(bf[j][1]));
                }
        }
        __syncthreads();

        // store prefetched tile
        if (it + 1 < iters) {
            *(float4*)&As[aRow][aC4] = make_float4(
                __uint_as_float(f2tf32(pa0.x)), __uint_as_float(f2tf32(pa0.y)),
                __uint_as_float(f2tf32(pa0.z)), __uint_as_float(f2tf32(pa0.w)));
            *(float4*)&As[aRow + 64][aC4] = make_float4(
                __uint_as_float(f2tf32(pa1.x)), __uint_as_float(f2tf32(pa1.y)),
                __uint_as_float(f2tf32(pa1.z)), __uint_as_float(f2tf32(pa1.w)));
            *(float4*)&Bs[bK][bN] = make_float4(
                __uint_as_float(f2tf32(pb0.x)), __uint_as_float(f2tf32(pb0.y)),
                __uint_as_float(f2tf32(pb0.z)), __uint_as_float(f2tf32(pb0.w)));
            *(float4*)&Bs[bK + 8][bN] = make_float4(
                __uint_as_float(f2tf32(pb1.x)), __uint_as_float(f2tf32(pb1.y)),
                __uint_as_float(f2tf32(pb1.z)), __uint_as_float(f2tf32(pb1.w)));
            __syncthreads();
        }
    }

    // epilogue: c0,c1 -> (row, 2c..2c+1); c2,c3 -> (row+8, 2c..2c+1)
#pragma unroll
    for (int i = 0; i < 4; i++) {
        const long long row = m0 + wm + i * 16 + (lane >> 2);
#pragma unroll
        for (int j = 0; j < 4; j++) {
            const int ncol = n0 + wn + j * 8 + (lane & 3) * 2;
            const int s  = ncol / CDIM;               // output tensor id
            const int cc = ncol - s * CDIM;
            float* Cp = (s == 0) ? C0 : ((s == 1) ? C1 : C2);
            const float bx = bias[ncol], by = bias[ncol + 1];
            float2 v0 = make_float2(acc[i][j][0] + bx, acc[i][j][1] + by);
            float2 v1 = make_float2(acc[i][j][2] + bx, acc[i][j][3] + by);
            *(float2*)(Cp + row * CDIM + cc)              = v0;
            *(float2*)(Cp + (row + 8) * CDIM + cc)        = v1;
        }
    }
}

// ---------------------------------------------------------------------------
// Attention: one block per (window b, head h). 256 threads.
//   S = (q*scale) @ k^T + rel_bias[h] + mask[b % NWIN]
//   P = softmax(S);  O = P @ v  -> g_att[b][n][h*32+d]
// ---------------------------------------------------------------------------
__global__ __launch_bounds__(256) void attn_kernel(
    const float* __restrict__ mask, const float* __restrict__ rel_bias,
    float* __restrict__ attout)
{
    const int bh = blockIdx.x;
    const int b  = bh / HEADS;
    const int h  = bh - b * HEADS;
    const int w  = b & (NWIN - 1);

    __shared__ float qs[NTOK * 33];
    __shared__ float ks[NTOK * 33];
    __shared__ float vs[NTOK * HD];
    __shared__ float sm[NTOK][56];

    const int tid = threadIdx.x;
    const float scale = 0.17677669529663689f;   // 1/sqrt(32)

    const long long base = ((long long)b * NTOK) * CDIM + h * HD;
    for (int idx = tid; idx < NTOK * HD; idx += 256) {
        const int n = idx >> 5, d = idx & 31;
        const long long g = base + (long long)n * CDIM + d;
        qs[n * 33 + d] = g_q[g] * scale;
        ks[n * 33 + d] = g_k[g];
        vs[n * HD + d] = g_v[g];
    }
    __syncthreads();

    const float* rb = rel_bias + h * (NTOK * NTOK);
    const float* mk = mask + (long long)w * (NTOK * NTOK);

    for (int idx = tid; idx < NTOK * NTOK; idx += 256) {
        const int i = idx / NTOK;
        const int j = idx - i * NTOK;
        float acc = 0.0f;
#pragma unroll
        for (int k = 0; k < HD; k++)
            acc = fmaf(qs[i * 33 + k], ks[j * 33 + k], acc);
        sm[i][j] = acc + rb[idx] + mk[idx];
    }
    __syncthreads();

    const int warp = tid >> 5, lane = tid & 31;
    for (int i = warp; i < NTOK; i += 8) {
        float m = -1e30f;
        for (int j = lane; j < NTOK; j += 32) m = fmaxf(m, sm[i][j]);
#pragma unroll
        for (int o = 16; o; o >>= 1) m = fmaxf(m, __shfl_xor_sync(0xffffffffu, m, o));
        float sum = 0.0f;
        for (int j = lane; j < NTOK; j += 32) {
            const float e = __expf(sm[i][j] - m);
            sm[i][j] = e;
            sum += e;
        }
#pragma unroll
        for (int o = 16; o; o >>= 1) sum += __shfl_xor_sync(0xffffffffu, sum, o);
        const float inv = 1.0f / sum;
        for (int j = lane; j < NTOK; j += 32) sm[i][j] *= inv;
    }
    __syncthreads();

    for (int idx = tid; idx < NTOK * HD; idx += 256) {
        const int i = idx >> 5, d = idx & 31;
        float acc = 0.0f;
#pragma unroll
        for (int j = 0; j < NTOK; j++)
            acc = fmaf(sm[i][j], vs[j * HD + d], acc);
        attout[((long long)b * NTOK + i) * CDIM + h * HD + d] = acc;
    }
}

// ---------------------------------------------------------------------------
extern "C" void kernel_launch(void* const* d_in, const int* in_sizes, int n_in,
                              void* d_out, int out_size)
{
    (void)in_sizes; (void)n_in; (void)out_size;
    const float* x        = (const float*)d_in[0];
    const float* mask     = (const float*)d_in[1];
    const float* qkv_w    = (const float*)d_in[2];
    const float* qkv_b    = (const float*)d_in[3];
    const float* rel_bias = (const float*)d_in[4];
    const float* proj_w   = (const float*)d_in[5];
    const float* proj_b   = (const float*)d_in[6];
    float* out = (float*)d_out;

    float *gq, *gk, *gv, *ga;
    cudaGetSymbolAddress((void**)&gq, g_q);
    cudaGetSymbolAddress((void**)&gk, g_k);
    cudaGetSymbolAddress((void**)&gv, g_v);
    cudaGetSymbolAddress((void**)&ga, g_att);

    // 1) QKV projection: (401408 x 384) @ (384 x 1152) + qkv_b -> g_q/g_k/g_v
    {
        dim3 grid(3 * CDIM / 128, MROWS / 128);
        gemm_tf32<<<grid, 256>>>(x, qkv_w, qkv_b, gq, gk, gv, CDIM, 3 * CDIM);
    }
    // 2) Attention per (window, head)
    {
        attn_kernel<<<BATCH * HEADS, 256>>>(mask, rel_bias, ga);
    }
    // 3) Output projection: (401408 x 384) @ (384 x 384) + proj_b -> d_out
    {
        dim3 grid(CDIM / 128, MROWS / 128);
        gemm_tf32<<<grid, 256>>>(ga, proj_w, proj_b, out, out, out, CDIM, CDIM);
    }
}

// round 3
// speedup vs baseline: 2.3035x; 1.0936x over previous
#include <cuda_runtime.h>
#include <cstdint>

// Problem constants
#define HEADS   12
#define NTOK    49
#define HD      32
#define CDIM    384
#define NWIN    1024
#define BATCH   8192
#define MROWS   (8192*49)        // 401408

// Scratch: __device__ globals (no allocation allowed in kernel_launch)
__device__ float g_q[(long long)MROWS * CDIM];
__device__ float g_k[(long long)MROWS * CDIM];
__device__ float g_v[(long long)MROWS * CDIM];
__device__ float g_att[(long long)MROWS * CDIM];

__device__ __forceinline__ uint32_t f2tf32(float f) {
    uint32_t u;
    asm("cvt.rna.tf32.f32 %0, %1;" : "=r"(u) : "f"(f));
    return u;
}
__device__ __forceinline__ float f2tf32f(float f) {
    return __uint_as_float(f2tf32(f));
}

// ---------------------------------------------------------------------------
// TF32 tensor-core GEMM v2: C = A(MxK) @ B(KxN) + bias, output routed to up
// to 3 row-major 384-col tensors. Tile 128x128x16, 256 threads (8 warps,
// 2m x 4n), warp tile 64x32, mma.m16n8k8.tf32.
// v2: B transposed in smem ([n][k]) so B fragments use ldmatrix.x4;
//     double-buffered smem, one sync per K-tile.
// ---------------------------------------------------------------------------
__global__ __launch_bounds__(256, 2) void gemm_tf32(
    const float* __restrict__ A, const float* __restrict__ B,
    const float* __restrict__ bias,
    float* __restrict__ C0, float* __restrict__ C1, float* __restrict__ C2,
    int K, int N)
{
    __shared__ float As[2][128][20];   // [stage][m][k] row stride 80B (16B mult)
    __shared__ float Bs[2][128][20];   // [stage][n][k] transposed B

    const int tid  = threadIdx.x;
    const int lane = tid & 31;
    const int wid  = tid >> 5;
    const int wm   = (wid & 1) * 64;
    const int wn   = (wid >> 1) * 32;

    const long long m0 = (long long)blockIdx.y * 128;
    const int       n0 = blockIdx.x * 128;

    // A global-load mapping: rows tid>>2 (+64), k-offset (tid&3)*4
    const int aRow = tid >> 2;
    const int aC4  = (tid & 3) * 4;
    const float* Ap = A + (m0 + aRow) * (long long)K + aC4;

    // B global-load mapping: each thread handles one n (tid&127) and 8 k's
    const int bN  = tid & 127;                 // n within tile
    const int bKh = (tid >> 7) * 8;            // k half: 0 or 8
    const float* Bp = B + n0 + bN;             // + (k)*N per element

    float acc[4][4][4];
#pragma unroll
    for (int i = 0; i < 4; i++)
#pragma unroll
        for (int j = 0; j < 4; j++)
#pragma unroll
            for (int r = 0; r < 4; r++) acc[i][j][r] = 0.0f;

    const int iters = K >> 4;

    float4 pa0, pa1;
    float  pb[8];

    // prefetch + store tile 0
    pa0 = *(const float4*)(Ap);
    pa1 = *(const float4*)(Ap + 64 * (long long)K);
#pragma unroll
    for (int j = 0; j < 8; j++) pb[j] = Bp[(long long)(bKh + j) * N];

    *(float4*)&As[0][aRow][aC4] = make_float4(
        f2tf32f(pa0.x), f2tf32f(pa0.y), f2tf32f(pa0.z), f2tf32f(pa0.w));
    *(float4*)&As[0][aRow + 64][aC4] = make_float4(
        f2tf32f(pa1.x), f2tf32f(pa1.y), f2tf32f(pa1.z), f2tf32f(pa1.w));
    *(float4*)&Bs[0][bN][bKh] = make_float4(
        f2tf32f(pb[0]), f2tf32f(pb[1]), f2tf32f(pb[2]), f2tf32f(pb[3]));
    *(float4*)&Bs[0][bN][bKh + 4] = make_float4(
        f2tf32f(pb[4]), f2tf32f(pb[5]), f2tf32f(pb[6]), f2tf32f(pb[7]));
    __syncthreads();

    // ldmatrix lane mappings
    const int lg     = lane >> 3;
    const int lr     = lane & 7;
    const int ldRow  = ((lg & 1) << 3) + lr;   // A: row within m16
    const int ldKoff = (lg >> 1) << 2;         // A: k offset 0/4
    const int bRowSel = ((lane >> 4) << 3) + (lane & 7);  // B: row within n16
    const int bKSel   = ((lane >> 3) & 1) << 2;           // B: k offset 0/4

    for (int it = 0; it < iters; ++it) {
        const int cur = it & 1;
        const bool more = (it + 1 < iters);

        if (more) {
            const long long kk = (long long)(it + 1) << 4;
            pa0 = *(const float4*)(Ap + kk);
            pa1 = *(const float4*)(Ap + 64 * (long long)K + kk);
#pragma unroll
            for (int j = 0; j < 8; j++) pb[j] = Bp[(kk + bKh + j) * N];
        }

#pragma unroll
        for (int ks = 0; ks < 2; ks++) {
            const int k0 = ks * 8;
            uint32_t af[4][4];
#pragma unroll
            for (int i = 0; i < 4; i++) {
                uint32_t sa = (uint32_t)__cvta_generic_to_shared(
                    &As[cur][wm + i * 16 + ldRow][k0 + ldKoff]);
                asm volatile(
                    "ldmatrix.sync.aligned.m8n8.x4.shared.b16 {%0,%1,%2,%3}, [%4];"
                    : "=r"(af[i][0]), "=r"(af[i][1]), "=r"(af[i][2]), "=r"(af[i][3])
                    : "r"(sa));
            }
            uint32_t bf[4][2];
#pragma unroll
            for (int jj = 0; jj < 2; jj++) {
                uint32_t sb = (uint32_t)__cvta_generic_to_shared(
                    &Bs[cur][wn + jj * 16 + bRowSel][k0 + bKSel]);
                uint32_t r0, r1, r2, r3;
                asm volatile(
                    "ldmatrix.sync.aligned.m8n8.x4.shared.b16 {%0,%1,%2,%3}, [%4];"
                    : "=r"(r0), "=r"(r1), "=r"(r2), "=r"(r3)
                    : "r"(sb));
                bf[jj * 2][0]     = r0; bf[jj * 2][1]     = r1;
                bf[jj * 2 + 1][0] = r2; bf[jj * 2 + 1][1] = r3;
            }
#pragma unroll
            for (int i = 0; i < 4; i++)
#pragma unroll
                for (int j = 0; j < 4; j++) {
                    asm volatile(
                        "mma.sync.aligned.m16n8k8.row.col.f32.tf32.tf32.f32 "
                        "{%0,%1,%2,%3}, {%4,%5,%6,%7}, {%8,%9}, {%0,%1,%2,%3};"
                        : "+f"(acc[i][j][0]), "+f"(acc[i][j][1]),
                          "+f"(acc[i][j][2]), "+f"(acc[i][j][3])
                        : "r"(af[i][0]), "r"(af[i][1]), "r"(af[i][2]), "r"(af[i][3]),
                          "r"(bf[j][0]), "r"(bf[j][1]));
                }
        }

        if (more) {
            const int nxt = cur ^ 1;
            *(float4*)&As[nxt][aRow][aC4] = make_float4(
                f2tf32f(pa0.x), f2tf32f(pa0.y), f2tf32f(pa0.z), f2tf32f(pa0.w));
            *(float4*)&As[nxt][aRow + 64][aC4] = make_float4(
                f2tf32f(pa1.x), f2tf32f(pa1.y), f2tf32f(pa1.z), f2tf32f(pa1.w));
            *(float4*)&Bs[nxt][bN][bKh] = make_float4(
                f2tf32f(pb[0]), f2tf32f(pb[1]), f2tf32f(pb[2]), f2tf32f(pb[3]));
            *(float4*)&Bs[nxt][bN][bKh + 4] = make_float4(
                f2tf32f(pb[4]), f2tf32f(pb[5]), f2tf32f(pb[6]), f2tf32f(pb[7]));
            __syncthreads();
        }
    }

    // epilogue
#pragma unroll
    for (int i = 0; i < 4; i++) {
        const long long row = m0 + wm + i * 16 + (lane >> 2);
#pragma unroll
        for (int j = 0; j < 4; j++) {
            const int ncol = n0 + wn + j * 8 + (lane & 3) * 2;
            const int s  = ncol / CDIM;
            const int cc = ncol - s * CDIM;
            float* Cp = (s == 0) ? C0 : ((s == 1) ? C1 : C2);
            const float bx = bias[ncol], by = bias[ncol + 1];
            *(float2*)(Cp + row * CDIM + cc) =
                make_float2(acc[i][j][0] + bx, acc[i][j][1] + by);
            *(float2*)(Cp + (row + 8) * CDIM + cc) =
                make_float2(acc[i][j][2] + bx, acc[i][j][3] + by);
        }
    }
}

// ---------------------------------------------------------------------------
// Attention v2: one block per (window b, head h). 256 threads.
// float4-vectorized inner loops to cut LDS-issue pressure.
// ---------------------------------------------------------------------------
__global__ __launch_bounds__(256) void attn_kernel(
    const float* __restrict__ mask, const float* __restrict__ rel_bias,
    float* __restrict__ attout)
{
    const int bh = blockIdx.x;
    const int b  = bh / HEADS;
    const int h  = bh - b * HEADS;
    const int w  = b & (NWIN - 1);

    __shared__ float qs[NTOK * 36];   // [n][k], stride 36 (144B, 16B-mult)
    __shared__ float ks[NTOK * 36];
    __shared__ float vs[NTOK * HD];   // [n][d], stride 32
    __shared__ float sm[NTOK][56];

    const int tid = threadIdx.x;
    const float scale = 0.17677669529663689f;   // 1/sqrt(32)

    const long long base = ((long long)b * NTOK) * CDIM + h * HD;
    for (int idx = tid; idx < NTOK * HD; idx += 256) {
        const int n = idx >> 5, d = idx & 31;
        const long long g = base + (long long)n * CDIM + d;
        qs[n * 36 + d] = g_q[g] * scale;
        ks[n * 36 + d] = g_k[g];
        vs[n * HD + d] = g_v[g];
    }
    __syncthreads();

    const float* rb = rel_bias + h * (NTOK * NTOK);
    const float* mk = mask + (long long)w * (NTOK * NTOK);

    // S = q*scale @ k^T + rel_bias + mask  (float4 along k)
    for (int idx = tid; idx < NTOK * NTOK; idx += 256) {
        const int i = idx / NTOK;
        const int j = idx - i * NTOK;
        float4 a4 = make_float4(0.f, 0.f, 0.f, 0.f);
#pragma unroll
        for (int k = 0; k < HD; k += 4) {
            const float4 qa = *(const float4*)&qs[i * 36 + k];
            const float4 kb = *(const float4*)&ks[j * 36 + k];
            a4.x = fmaf(qa.x, kb.x, a4.x);
            a4.y = fmaf(qa.y, kb.y, a4.y);
            a4.z = fmaf(qa.z, kb.z, a4.z);
            a4.w = fmaf(qa.w, kb.w, a4.w);
        }
        sm[i][j] = (a4.x + a4.y) + (a4.z + a4.w) + rb[idx] + mk[idx];
    }
    __syncthreads();

    // softmax, warp per row
    const int warp = tid >> 5, lane = tid & 31;
    for (int i = warp; i < NTOK; i += 8) {
        float m = -1e30f;
        for (int j = lane; j < NTOK; j += 32) m = fmaxf(m, sm[i][j]);
#pragma unroll
        for (int o = 16; o; o >>= 1) m = fmaxf(m, __shfl_xor_sync(0xffffffffu, m, o));
        float sum = 0.0f;
        for (int j = lane; j < NTOK; j += 32) {
            const float e = __expf(sm[i][j] - m);
            sm[i][j] = e;
            sum += e;
        }
#pragma unroll
        for (int o = 16; o; o >>= 1) sum += __shfl_xor_sync(0xffffffffu, sum, o);
        const float inv = 1.0f / sum;
        for (int j = lane; j < NTOK; j += 32) sm[i][j] *= inv;
    }
    __syncthreads();

    // O = P @ V : each work item = (row i, 4 head-dims)
    for (int idx = tid; idx < NTOK * (HD / 4); idx += 256) {
        const int i  = idx >> 3;
        const int d4 = (idx & 7) << 2;
        float4 a4 = make_float4(0.f, 0.f, 0.f, 0.f);
#pragma unroll 7
        for (int j = 0; j < NTOK; j++) {
            const float s = sm[i][j];
            const float4 v = *(const float4*)&vs[j * HD + d4];
            a4.x = fmaf(s, v.x, a4.x);
            a4.y = fmaf(s, v.y, a4.y);
            a4.z = fmaf(s, v.z, a4.z);
            a4.w = fmaf(s, v.w, a4.w);
        }
        *(float4*)&attout[((long long)b * NTOK + i) * CDIM + h * HD + d4] = a4;
    }
}

// ---------------------------------------------------------------------------
extern "C" void kernel_launch(void* const* d_in, const int* in_sizes, int n_in,
                              void* d_out, int out_size)
{
    (void)in_sizes; (void)n_in; (void)out_size;
    const float* x        = (const float*)d_in[0];
    const float* mask     = (const float*)d_in[1];
    const float* qkv_w    = (const float*)d_in[2];
    const float* qkv_b    = (const float*)d_in[3];
    const float* rel_bias = (const float*)d_in[4];
    const float* proj_w   = (const float*)d_in[5];
    const float* proj_b   = (const float*)d_in[6];
    float* out = (float*)d_out;

    float *gq, *gk, *gv, *ga;
    cudaGetSymbolAddress((void**)&gq, g_q);
    cudaGetSymbolAddress((void**)&gk, g_k);
    cudaGetSymbolAddress((void**)&gv, g_v);
    cudaGetSymbolAddress((void**)&ga, g_att);

    // 1) QKV projection: (401408 x 384) @ (384 x 1152) + qkv_b -> g_q/g_k/g_v
    {
        dim3 grid(3 * CDIM / 128, MROWS / 128);
        gemm_tf32<<<grid, 256>>>(x, qkv_w, qkv_b, gq, gk, gv, CDIM, 3 * CDIM);
    }
    // 2) Attention per (window, head)
    {
        attn_kernel<<<BATCH * HEADS, 256>>>(mask, rel_bias, ga);
    }
    // 3) Output projection: (401408 x 384) @ (384 x 384) + proj_b -> d_out
    {
        dim3 grid(CDIM / 128, MROWS / 128);
        gemm_tf32<<<grid, 256>>>(ga, proj_w, proj_b, out, out, out, CDIM, CDIM);
    }
}